// round 2
// baseline (speedup 1.0000x reference)
#include <cuda_runtime.h>
#include <math.h>
#include <stdint.h>

// ---------------------------------------------------------------------------
// ODE-RNN encoder. T=64, B=1024, OBS=8, HID=512, RK4 with 4 steps.
// Structure:
//   1) obs->hidden (Linear+LN+LeakyReLU) for all T*B rows at once.
//   2) RK4 over t in [0,1]: 16 ode_f evals, each 3 GEMMs [65536,512]x[512,512]
//      with fused LN+LeakyReLU epilogues; RK4 state updates fused into the
//      3rd GEMM's epilogue. All timesteps batched (ODE is independent of h_prev).
//   3) gi = h_ode @ W_ih + b_ih precomputed batched for all T.
//   4) Sequential GRU over T=64: gh GEMM + elementwise gate kernel.
// fp32 throughout, using packed fma.rn.f32x2 (Blackwell dual-FMA pipe).
// ---------------------------------------------------------------------------

#define HID   512
#define TT    64
#define BB    1024
#define TB    65536           // TT*BB
#define NS3   ((size_t)TB * HID)

// scratch: H, S, A, Z1, Z2 (each TB*HID) + GI (TB*1536) + GH (BB*1536)
#define BUF_TOTAL (5*65536*512 + 65536*1536 + 1024*1536)
__device__ float g_buf[BUF_TOTAL];

typedef unsigned long long u64;

__device__ __forceinline__ u64 pack2(float lo, float hi) {
    u64 r; asm("mov.b64 %0, {%1, %2};" : "=l"(r) : "f"(lo), "f"(hi)); return r;
}
__device__ __forceinline__ float2 unpack2(u64 v) {
    float2 r; asm("mov.b64 {%0, %1}, %2;" : "=f"(r.x), "=f"(r.y) : "l"(v)); return r;
}
__device__ __forceinline__ void ffma2(u64& d, u64 a, u64 b) {
    asm("fma.rn.f32x2 %0, %1, %2, %0;" : "+l"(d) : "l"(a), "l"(b));
}

// ---------------------------------------------------------------------------
// zero-fill (h_prev = 0)
// ---------------------------------------------------------------------------
__global__ void zero_kernel(float* __restrict__ p, int n) {
    int i = blockIdx.x * blockDim.x + threadIdx.x;
    if (i < n) p[i] = 0.0f;
}

// ---------------------------------------------------------------------------
// obs2hidden: y = leaky(LN(x @ obs_W + obs_b)). One warp per row.
// xs: [TB, 8], obs_W: [8, 512]. Output H: [TB, 512].
// ---------------------------------------------------------------------------
__global__ void __launch_bounds__(256) obs_kernel(
    const float* __restrict__ xs, const float* __restrict__ W,
    const float* __restrict__ b, const float* __restrict__ g,
    const float* __restrict__ bb, float* __restrict__ H)
{
    int row  = blockIdx.x * 8 + (threadIdx.x >> 5);
    int lane = threadIdx.x & 31;
    const float* x = xs + (size_t)row * 8;
    float xv[8];
#pragma unroll
    for (int j = 0; j < 8; j++) xv[j] = x[j];

    float y[16], s = 0.f, sq = 0.f;
#pragma unroll
    for (int i = 0; i < 16; i++) {
        int c = lane + i * 32;
        float acc = b[c];
#pragma unroll
        for (int j = 0; j < 8; j++) acc += xv[j] * W[j * 512 + c];
        y[i] = acc; s += acc; sq += acc * acc;
    }
#pragma unroll
    for (int o = 16; o > 0; o >>= 1) {
        s  += __shfl_xor_sync(0xffffffffu, s,  o);
        sq += __shfl_xor_sync(0xffffffffu, sq, o);
    }
    float m   = s * (1.f / 512.f);
    float var = sq * (1.f / 512.f) - m * m;
    float inv = rsqrtf(var + 1e-5f);
#pragma unroll
    for (int i = 0; i < 16; i++) {
        int c = lane + i * 32;
        float v = (y[i] - m) * inv * g[c] + bb[c];
        H[(size_t)row * 512 + c] = (v > 0.f) ? v : 0.01f * v;
    }
}

// ---------------------------------------------------------------------------
// Fused GEMM: C[M, Ncols] = X[M,512] @ W[512, Ntot] (+ epilogue).
// Tile: BM=32 rows x 512 cols per CTA, 256 threads (8 warps).
// Thread (ty,tx): rows ty*4..+3, col pairs {tx*2 + j*64} j=0..7.
// Packed f32x2 FMA in the inner loop.
// MODE 0: out = leaky(LN(acc + bias [+ t*wlast])), N must be 512 (full row in CTA).
// MODE 1: out[row*N + col] = acc + bias (plain, N can be 1536 via blockIdx.y).
// MODE 2: RK4 epilogue: k = acc + bias;
//    stage 0: A = h + (dt/6)k ; S = h + (dt/2)k
//    stage 1: A += (dt/3)k    ; S = h + (dt/2)k
//    stage 2: A += (dt/3)k    ; S = h + dt*k
//    stage 3: sout = A + (dt/6)k   (new H)
// ---------------------------------------------------------------------------
template<int MODE>
__global__ void __launch_bounds__(256) gemm_fused(
    const float* __restrict__ X, const float* __restrict__ W, int N,
    const float* __restrict__ bias, const float* __restrict__ wlast, float tval,
    const float* __restrict__ lng, const float* __restrict__ lnb,
    float* __restrict__ out,
    const float* __restrict__ hin, float* __restrict__ accb,
    float* __restrict__ sout, int stage)
{
    __shared__ float As[16][33];
    __shared__ float Bs[16][512];

    const int tid  = threadIdx.x;
    const int tx   = tid & 31;
    const int ty   = tid >> 5;
    const int row0 = blockIdx.x * 32;
    const int col0 = blockIdx.y * 512;

    u64 acc[4][8];
#pragma unroll
    for (int r = 0; r < 4; r++)
#pragma unroll
        for (int j = 0; j < 8; j++) acc[r][j] = 0ull;

    const int lm = tid >> 3;        // 0..31 (row within tile)
    const int lk = (tid & 7) * 2;   // 0,2,..,14 (k within chunk)

    for (int k0 = 0; k0 < 512; k0 += 16) {
        float2 av = *(const float2*)(X + (size_t)(row0 + lm) * 512 + k0 + lk);
        As[lk][lm]     = av.x;
        As[lk + 1][lm] = av.y;
#pragma unroll
        for (int i = 0; i < 8; i++) {
            int lin = tid + i * 256;       // 0..2047 float4 index
            int k   = lin >> 7;            // 0..15
            int c   = (lin & 127) * 4;     // 0..508
            *(float4*)&Bs[k][c] =
                *(const float4*)(W + (size_t)(k0 + k) * N + col0 + c);
        }
        __syncthreads();
#pragma unroll
        for (int k = 0; k < 16; k++) {
            u64 a[4];
#pragma unroll
            for (int r = 0; r < 4; r++) {
                float v = As[k][ty * 4 + r];
                a[r] = pack2(v, v);
            }
#pragma unroll
            for (int j = 0; j < 8; j++) {
                float2 bv = *(const float2*)&Bs[k][tx * 2 + j * 64];
                u64 bp = pack2(bv.x, bv.y);
#pragma unroll
                for (int r = 0; r < 4; r++) ffma2(acc[r][j], a[r], bp);
            }
        }
        __syncthreads();
    }

    // ---------------- epilogue ----------------
#pragma unroll
    for (int r = 0; r < 4; r++) {
        const int row = row0 + ty * 4 + r;
        if (MODE == 0) {
            float vals[16], s = 0.f, sq = 0.f;
#pragma unroll
            for (int j = 0; j < 8; j++) {
                int c = tx * 2 + j * 64;
                float2 v  = unpack2(acc[r][j]);
                float2 bz = *(const float2*)&bias[c];
                v.x += bz.x; v.y += bz.y;
                if (wlast) {
                    float2 wl = *(const float2*)&wlast[c];
                    v.x += tval * wl.x; v.y += tval * wl.y;
                }
                vals[2 * j] = v.x; vals[2 * j + 1] = v.y;
                s  += v.x + v.y;
                sq += v.x * v.x + v.y * v.y;
            }
#pragma unroll
            for (int o = 16; o > 0; o >>= 1) {
                s  += __shfl_xor_sync(0xffffffffu, s,  o);
                sq += __shfl_xor_sync(0xffffffffu, sq, o);
            }
            float m   = s * (1.f / 512.f);
            float var = sq * (1.f / 512.f) - m * m;
            float inv = rsqrtf(var + 1e-5f);
#pragma unroll
            for (int j = 0; j < 8; j++) {
                int c = tx * 2 + j * 64;
                float2 gg  = *(const float2*)&lng[c];
                float2 bb2 = *(const float2*)&lnb[c];
                float2 o2;
                o2.x = (vals[2 * j]     - m) * inv * gg.x + bb2.x;
                o2.y = (vals[2 * j + 1] - m) * inv * gg.y + bb2.y;
                o2.x = (o2.x > 0.f) ? o2.x : 0.01f * o2.x;
                o2.y = (o2.y > 0.f) ? o2.y : 0.01f * o2.y;
                *(float2*)(out + (size_t)row * 512 + c) = o2;
            }
        } else if (MODE == 1) {
#pragma unroll
            for (int j = 0; j < 8; j++) {
                int c  = tx * 2 + j * 64;
                int gc = col0 + c;
                float2 v  = unpack2(acc[r][j]);
                float2 bz = *(const float2*)&bias[gc];
                v.x += bz.x; v.y += bz.y;
                *(float2*)(out + (size_t)row * N + gc) = v;
            }
        } else {
            const float dt6 = 0.25f / 6.f;
            const float dt3 = 0.25f / 3.f;
            float cS = (stage < 2) ? 0.125f : 0.25f;
#pragma unroll
            for (int j = 0; j < 8; j++) {
                int c = tx * 2 + j * 64;
                float2 kv = unpack2(acc[r][j]);
                float2 bz = *(const float2*)&bias[c];
                kv.x += bz.x; kv.y += bz.y;
                size_t idx = (size_t)row * 512 + c;
                if (stage == 3) {
                    float2 a = *(const float2*)&accb[idx];
                    float2 hn;
                    hn.x = a.x + dt6 * kv.x;
                    hn.y = a.y + dt6 * kv.y;
                    *(float2*)&sout[idx] = hn;
                } else {
                    float2 h2 = *(const float2*)&hin[idx];
                    float2 a;
                    if (stage == 0) {
                        a.x = h2.x + dt6 * kv.x;
                        a.y = h2.y + dt6 * kv.y;
                    } else {
                        a = *(const float2*)&accb[idx];
                        a.x += dt3 * kv.x;
                        a.y += dt3 * kv.y;
                    }
                    *(float2*)&accb[idx] = a;
                    float2 s2;
                    s2.x = h2.x + cS * kv.x;
                    s2.y = h2.y + cS * kv.y;
                    *(float2*)&sout[idx] = s2;
                }
            }
        }
    }
}

// ---------------------------------------------------------------------------
// GRU gate combine: h = (1-z)*n + z*h, in-place on h.
// gi, gh: [B, 1536] (order r, z, n). h: [B, 512].
// ---------------------------------------------------------------------------
__global__ void __launch_bounds__(256) gru_gate(
    const float* __restrict__ gi, const float* __restrict__ gh,
    float* __restrict__ h)
{
    int idx = blockIdx.x * 256 + threadIdx.x;   // 0 .. B*512-1
    int b = idx >> 9;
    int c = idx & 511;
    size_t o = (size_t)b * 1536 + c;
    float ir = gi[o],        hr = gh[o];
    float iz = gi[o + 512],  hz = gh[o + 512];
    float in_ = gi[o + 1024], hn = gh[o + 1024];
    float r = 1.f / (1.f + expf(-(ir + hr)));
    float z = 1.f / (1.f + expf(-(iz + hz)));
    float n = tanhf(in_ + r * hn);
    h[idx] = (1.f - z) * n + z * h[idx];
}

// ---------------------------------------------------------------------------
// launch
// ---------------------------------------------------------------------------
extern "C" void kernel_launch(void* const* d_in, const int* in_sizes, int n_in,
                              void* d_out, int out_size)
{
    const float* xs     = (const float*)d_in[0];
    const float* obs_W  = (const float*)d_in[1];
    const float* obs_b  = (const float*)d_in[2];
    const float* obs_g  = (const float*)d_in[3];
    const float* obs_bb = (const float*)d_in[4];
    const float* W1     = (const float*)d_in[5];   // [513, 512]
    const float* b1     = (const float*)d_in[6];
    const float* g1     = (const float*)d_in[7];
    const float* bb1    = (const float*)d_in[8];
    const float* W2     = (const float*)d_in[9];
    const float* b2     = (const float*)d_in[10];
    const float* g2     = (const float*)d_in[11];
    const float* bb2    = (const float*)d_in[12];
    const float* Wout   = (const float*)d_in[13];
    const float* bout   = (const float*)d_in[14];
    const float* W_ih   = (const float*)d_in[15];  // [512, 1536]
    const float* b_ih   = (const float*)d_in[16];
    const float* W_hh   = (const float*)d_in[17];  // [512, 1536]
    const float* b_hh   = (const float*)d_in[18];
    float* hout = (float*)d_out;                   // [1024, 512], used as h state

    float* buf = nullptr;
    cudaGetSymbolAddress((void**)&buf, g_buf);
    float* H  = buf;
    float* S  = buf + NS3;
    float* A  = buf + 2 * NS3;
    float* Z1 = buf + 3 * NS3;
    float* Z2 = buf + 4 * NS3;
    float* GI = buf + 5 * NS3;
    float* GH = GI + (size_t)TB * 1536;

    // h_prev = 0
    zero_kernel<<<(BB * HID) / 256, 256>>>(hout, BB * HID);

    // obs -> hidden for all T*B rows
    obs_kernel<<<TB / 8, 256>>>(xs, obs_W, obs_b, obs_g, obs_bb, H);

    // batched RK4 over all timesteps (independent of GRU state)
    const float dt = 0.25f;
    const float* wlast = W1 + (size_t)512 * 512;   // time-concat row of ode_W1
    for (int s = 0; s < 4; s++) {
        float t0 = s * dt;
        float tv[4] = { t0, t0 + 0.125f, t0 + 0.125f, t0 + 0.25f };
        for (int e = 0; e < 4; e++) {
            const float* xin = (e == 0) ? H : S;
            gemm_fused<0><<<dim3(TB / 32, 1), 256>>>(
                xin, W1, 512, b1, wlast, tv[e], g1, bb1, Z1,
                nullptr, nullptr, nullptr, 0);
            gemm_fused<0><<<dim3(TB / 32, 1), 256>>>(
                Z1, W2, 512, b2, nullptr, 0.f, g2, bb2, Z2,
                nullptr, nullptr, nullptr, 0);
            gemm_fused<2><<<dim3(TB / 32, 1), 256>>>(
                Z2, Wout, 512, bout, nullptr, 0.f, nullptr, nullptr, nullptr,
                H, A, (e < 3) ? S : H, e);
        }
    }

    // gi for all timesteps in one batched GEMM
    gemm_fused<1><<<dim3(TB / 32, 3), 256>>>(
        H, W_ih, 1536, b_ih, nullptr, 0.f, nullptr, nullptr, GI,
        nullptr, nullptr, nullptr, 0);

    // sequential GRU over T
    for (int t = 0; t < TT; t++) {
        gemm_fused<1><<<dim3(BB / 32, 3), 256>>>(
            hout, W_hh, 1536, b_hh, nullptr, 0.f, nullptr, nullptr, GH,
            nullptr, nullptr, nullptr, 0);
        gru_gate<<<(BB * HID) / 256, 256>>>(
            GI + (size_t)t * BB * 1536, GH, hout);
    }
}

// round 3
// speedup vs baseline: 1.0050x; 1.0050x over previous
#include <cuda_runtime.h>
#include <math.h>
#include <stdint.h>

// ---------------------------------------------------------------------------
// ODE-RNN encoder. T=64, B=1024, OBS=8, HID=512, RK4 with 4 steps.
// Structure:
//   1) obs->hidden (Linear+LN+LeakyReLU) for all T*B rows at once.
//   2) RK4 over t in [0,1]: 16 ode_f evals, each 3 GEMMs [65536,512]x[512,512]
//      with fused LN+LeakyReLU epilogues; RK4 state updates fused into the
//      3rd GEMM's epilogue. All timesteps batched (ODE is independent of h_prev).
//   3) gi = h_ode @ W_ih + b_ih precomputed batched for all T.
//   4) Sequential GRU over T=64: gh GEMM + elementwise gate kernel.
// fp32 throughout, using packed fma.rn.f32x2 (Blackwell dual-FMA pipe).
// ---------------------------------------------------------------------------

#define HID   512
#define TT    64
#define BB    1024
#define TB    65536           // TT*BB
#define NS3   ((size_t)TB * HID)

// scratch: H, S, A, Z1, Z2 (each TB*HID) + GI (TB*1536) + GH (BB*1536)
#define BUF_TOTAL (5*65536*512 + 65536*1536 + 1024*1536)
__device__ float g_buf[BUF_TOTAL];

typedef unsigned long long u64;

__device__ __forceinline__ u64 pack2(float lo, float hi) {
    u64 r; asm("mov.b64 %0, {%1, %2};" : "=l"(r) : "f"(lo), "f"(hi)); return r;
}
__device__ __forceinline__ float2 unpack2(u64 v) {
    float2 r; asm("mov.b64 {%0, %1}, %2;" : "=f"(r.x), "=f"(r.y) : "l"(v)); return r;
}
__device__ __forceinline__ void ffma2(u64& d, u64 a, u64 b) {
    asm("fma.rn.f32x2 %0, %1, %2, %0;" : "+l"(d) : "l"(a), "l"(b));
}

// ---------------------------------------------------------------------------
// zero-fill (h_prev = 0)
// ---------------------------------------------------------------------------
__global__ void zero_kernel(float* __restrict__ p, int n) {
    int i = blockIdx.x * blockDim.x + threadIdx.x;
    if (i < n) p[i] = 0.0f;
}

// ---------------------------------------------------------------------------
// obs2hidden: y = leaky(LN(x @ obs_W + obs_b)). One warp per row.
// xs: [TB, 8], obs_W: [8, 512]. Output H: [TB, 512].
// ---------------------------------------------------------------------------
__global__ void __launch_bounds__(256) obs_kernel(
    const float* __restrict__ xs, const float* __restrict__ W,
    const float* __restrict__ b, const float* __restrict__ g,
    const float* __restrict__ bb, float* __restrict__ H)
{
    int row  = blockIdx.x * 8 + (threadIdx.x >> 5);
    int lane = threadIdx.x & 31;
    const float* x = xs + (size_t)row * 8;
    float xv[8];
#pragma unroll
    for (int j = 0; j < 8; j++) xv[j] = x[j];

    float y[16], s = 0.f, sq = 0.f;
#pragma unroll
    for (int i = 0; i < 16; i++) {
        int c = lane + i * 32;
        float acc = b[c];
#pragma unroll
        for (int j = 0; j < 8; j++) acc += xv[j] * W[j * 512 + c];
        y[i] = acc; s += acc; sq += acc * acc;
    }
#pragma unroll
    for (int o = 16; o > 0; o >>= 1) {
        s  += __shfl_xor_sync(0xffffffffu, s,  o);
        sq += __shfl_xor_sync(0xffffffffu, sq, o);
    }
    float m   = s * (1.f / 512.f);
    float var = sq * (1.f / 512.f) - m * m;
    float inv = rsqrtf(var + 1e-5f);
#pragma unroll
    for (int i = 0; i < 16; i++) {
        int c = lane + i * 32;
        float v = (y[i] - m) * inv * g[c] + bb[c];
        H[(size_t)row * 512 + c] = (v > 0.f) ? v : 0.01f * v;
    }
}

// ---------------------------------------------------------------------------
// Fused GEMM: C[M, Ncols] = X[M,512] @ W[512, Ntot] (+ epilogue).
// Tile: BM=32 rows x 512 cols per CTA, 256 threads (8 warps).
// Thread (ty,tx): rows ty*4..+3, col pairs {tx*2 + j*64} j=0..7.
// Packed f32x2 FMA in the inner loop.
// MODE 0: out = leaky(LN(acc + bias [+ t*wlast])), N must be 512 (full row in CTA).
// MODE 1: out[row*N + col] = acc + bias (plain, N can be 1536 via blockIdx.y).
// MODE 2: RK4 epilogue: k = acc + bias;
//    stage 0: A = h + (dt/6)k ; S = h + (dt/2)k
//    stage 1: A += (dt/3)k    ; S = h + (dt/2)k
//    stage 2: A += (dt/3)k    ; S = h + dt*k
//    stage 3: sout = A + (dt/6)k   (new H)
// ---------------------------------------------------------------------------
template<int MODE>
__global__ void __launch_bounds__(256) gemm_fused(
    const float* __restrict__ X, const float* __restrict__ W, int N,
    const float* __restrict__ bias, const float* __restrict__ wlast, float tval,
    const float* __restrict__ lng, const float* __restrict__ lnb,
    float* __restrict__ out,
    const float* __restrict__ hin, float* __restrict__ accb,
    float* __restrict__ sout, int stage)
{
    __shared__ float As[16][33];
    __shared__ float Bs[16][512];

    const int tid  = threadIdx.x;
    const int tx   = tid & 31;
    const int ty   = tid >> 5;
    const int row0 = blockIdx.x * 32;
    const int col0 = blockIdx.y * 512;

    u64 acc[4][8];
#pragma unroll
    for (int r = 0; r < 4; r++)
#pragma unroll
        for (int j = 0; j < 8; j++) acc[r][j] = 0ull;

    const int lm = tid >> 3;        // 0..31 (row within tile)
    const int lk = (tid & 7) * 2;   // 0,2,..,14 (k within chunk)

    for (int k0 = 0; k0 < 512; k0 += 16) {
        float2 av = *(const float2*)(X + (size_t)(row0 + lm) * 512 + k0 + lk);
        As[lk][lm]     = av.x;
        As[lk + 1][lm] = av.y;
#pragma unroll
        for (int i = 0; i < 8; i++) {
            int lin = tid + i * 256;       // 0..2047 float4 index
            int k   = lin >> 7;            // 0..15
            int c   = (lin & 127) * 4;     // 0..508
            *(float4*)&Bs[k][c] =
                *(const float4*)(W + (size_t)(k0 + k) * N + col0 + c);
        }
        __syncthreads();
#pragma unroll
        for (int k = 0; k < 16; k++) {
            u64 a[4];
#pragma unroll
            for (int r = 0; r < 4; r++) {
                float v = As[k][ty * 4 + r];
                a[r] = pack2(v, v);
            }
#pragma unroll
            for (int j = 0; j < 8; j++) {
                float2 bv = *(const float2*)&Bs[k][tx * 2 + j * 64];
                u64 bp = pack2(bv.x, bv.y);
#pragma unroll
                for (int r = 0; r < 4; r++) ffma2(acc[r][j], a[r], bp);
            }
        }
        __syncthreads();
    }

    // ---------------- epilogue ----------------
#pragma unroll
    for (int r = 0; r < 4; r++) {
        const int row = row0 + ty * 4 + r;
        if (MODE == 0) {
            float vals[16], s = 0.f, sq = 0.f;
#pragma unroll
            for (int j = 0; j < 8; j++) {
                int c = tx * 2 + j * 64;
                float2 v  = unpack2(acc[r][j]);
                float2 bz = *(const float2*)&bias[c];
                v.x += bz.x; v.y += bz.y;
                if (wlast) {
                    float2 wl = *(const float2*)&wlast[c];
                    v.x += tval * wl.x; v.y += tval * wl.y;
                }
                vals[2 * j] = v.x; vals[2 * j + 1] = v.y;
                s  += v.x + v.y;
                sq += v.x * v.x + v.y * v.y;
            }
#pragma unroll
            for (int o = 16; o > 0; o >>= 1) {
                s  += __shfl_xor_sync(0xffffffffu, s,  o);
                sq += __shfl_xor_sync(0xffffffffu, sq, o);
            }
            float m   = s * (1.f / 512.f);
            float var = sq * (1.f / 512.f) - m * m;
            float inv = rsqrtf(var + 1e-5f);
#pragma unroll
            for (int j = 0; j < 8; j++) {
                int c = tx * 2 + j * 64;
                float2 gg  = *(const float2*)&lng[c];
                float2 bb2 = *(const float2*)&lnb[c];
                float2 o2;
                o2.x = (vals[2 * j]     - m) * inv * gg.x + bb2.x;
                o2.y = (vals[2 * j + 1] - m) * inv * gg.y + bb2.y;
                o2.x = (o2.x > 0.f) ? o2.x : 0.01f * o2.x;
                o2.y = (o2.y > 0.f) ? o2.y : 0.01f * o2.y;
                *(float2*)(out + (size_t)row * 512 + c) = o2;
            }
        } else if (MODE == 1) {
#pragma unroll
            for (int j = 0; j < 8; j++) {
                int c  = tx * 2 + j * 64;
                int gc = col0 + c;
                float2 v  = unpack2(acc[r][j]);
                float2 bz = *(const float2*)&bias[gc];
                v.x += bz.x; v.y += bz.y;
                *(float2*)(out + (size_t)row * N + gc) = v;
            }
        } else {
            const float dt6 = 0.25f / 6.f;
            const float dt3 = 0.25f / 3.f;
            float cS = (stage < 2) ? 0.125f : 0.25f;
#pragma unroll
            for (int j = 0; j < 8; j++) {
                int c = tx * 2 + j * 64;
                float2 kv = unpack2(acc[r][j]);
                float2 bz = *(const float2*)&bias[c];
                kv.x += bz.x; kv.y += bz.y;
                size_t idx = (size_t)row * 512 + c;
                if (stage == 3) {
                    float2 a = *(const float2*)&accb[idx];
                    float2 hn;
                    hn.x = a.x + dt6 * kv.x;
                    hn.y = a.y + dt6 * kv.y;
                    *(float2*)&sout[idx] = hn;
                } else {
                    float2 h2 = *(const float2*)&hin[idx];
                    float2 a;
                    if (stage == 0) {
                        a.x = h2.x + dt6 * kv.x;
                        a.y = h2.y + dt6 * kv.y;
                    } else {
                        a = *(const float2*)&accb[idx];
                        a.x += dt3 * kv.x;
                        a.y += dt3 * kv.y;
                    }
                    *(float2*)&accb[idx] = a;
                    float2 s2;
                    s2.x = h2.x + cS * kv.x;
                    s2.y = h2.y + cS * kv.y;
                    *(float2*)&sout[idx] = s2;
                }
            }
        }
    }
}

// ---------------------------------------------------------------------------
// GRU gate combine: h = (1-z)*n + z*h, in-place on h.
// gi, gh: [B, 1536] (order r, z, n). h: [B, 512].
// ---------------------------------------------------------------------------
__global__ void __launch_bounds__(256) gru_gate(
    const float* __restrict__ gi, const float* __restrict__ gh,
    float* __restrict__ h)
{
    int idx = blockIdx.x * 256 + threadIdx.x;   // 0 .. B*512-1
    int b = idx >> 9;
    int c = idx & 511;
    size_t o = (size_t)b * 1536 + c;
    float ir = gi[o],        hr = gh[o];
    float iz = gi[o + 512],  hz = gh[o + 512];
    float in_ = gi[o + 1024], hn = gh[o + 1024];
    float r = 1.f / (1.f + expf(-(ir + hr)));
    float z = 1.f / (1.f + expf(-(iz + hz)));
    float n = tanhf(in_ + r * hn);
    h[idx] = (1.f - z) * n + z * h[idx];
}

// ---------------------------------------------------------------------------
// launch
// ---------------------------------------------------------------------------
extern "C" void kernel_launch(void* const* d_in, const int* in_sizes, int n_in,
                              void* d_out, int out_size)
{
    const float* xs     = (const float*)d_in[0];
    const float* obs_W  = (const float*)d_in[1];
    const float* obs_b  = (const float*)d_in[2];
    const float* obs_g  = (const float*)d_in[3];
    const float* obs_bb = (const float*)d_in[4];
    const float* W1     = (const float*)d_in[5];   // [513, 512]
    const float* b1     = (const float*)d_in[6];
    const float* g1     = (const float*)d_in[7];
    const float* bb1    = (const float*)d_in[8];
    const float* W2     = (const float*)d_in[9];
    const float* b2     = (const float*)d_in[10];
    const float* g2     = (const float*)d_in[11];
    const float* bb2    = (const float*)d_in[12];
    const float* Wout   = (const float*)d_in[13];
    const float* bout   = (const float*)d_in[14];
    const float* W_ih   = (const float*)d_in[15];  // [512, 1536]
    const float* b_ih   = (const float*)d_in[16];
    const float* W_hh   = (const float*)d_in[17];  // [512, 1536]
    const float* b_hh   = (const float*)d_in[18];
    float* hout = (float*)d_out;                   // [1024, 512], used as h state

    float* buf = nullptr;
    cudaGetSymbolAddress((void**)&buf, g_buf);
    float* H  = buf;
    float* S  = buf + NS3;
    float* A  = buf + 2 * NS3;
    float* Z1 = buf + 3 * NS3;
    float* Z2 = buf + 4 * NS3;
    float* GI = buf + 5 * NS3;
    float* GH = GI + (size_t)TB * 1536;

    // h_prev = 0
    zero_kernel<<<(BB * HID) / 256, 256>>>(hout, BB * HID);

    // obs -> hidden for all T*B rows
    obs_kernel<<<TB / 8, 256>>>(xs, obs_W, obs_b, obs_g, obs_bb, H);

    // batched RK4 over all timesteps (independent of GRU state)
    const float dt = 0.25f;
    const float* wlast = W1 + (size_t)512 * 512;   // time-concat row of ode_W1
    for (int s = 0; s < 4; s++) {
        float t0 = s * dt;
        float tv[4] = { t0, t0 + 0.125f, t0 + 0.125f, t0 + 0.25f };
        for (int e = 0; e < 4; e++) {
            const float* xin = (e == 0) ? H : S;
            gemm_fused<0><<<dim3(TB / 32, 1), 256>>>(
                xin, W1, 512, b1, wlast, tv[e], g1, bb1, Z1,
                nullptr, nullptr, nullptr, 0);
            gemm_fused<0><<<dim3(TB / 32, 1), 256>>>(
                Z1, W2, 512, b2, nullptr, 0.f, g2, bb2, Z2,
                nullptr, nullptr, nullptr, 0);
            gemm_fused<2><<<dim3(TB / 32, 1), 256>>>(
                Z2, Wout, 512, bout, nullptr, 0.f, nullptr, nullptr, nullptr,
                H, A, (e < 3) ? S : H, e);
        }
    }

    // gi for all timesteps in one batched GEMM
    gemm_fused<1><<<dim3(TB / 32, 3), 256>>>(
        H, W_ih, 1536, b_ih, nullptr, 0.f, nullptr, nullptr, GI,
        nullptr, nullptr, nullptr, 0);

    // sequential GRU over T
    for (int t = 0; t < TT; t++) {
        gemm_fused<1><<<dim3(BB / 32, 3), 256>>>(
            hout, W_hh, 1536, b_hh, nullptr, 0.f, nullptr, nullptr, GH,
            nullptr, nullptr, nullptr, 0);
        gru_gate<<<(BB * HID) / 256, 256>>>(
            GI + (size_t)t * BB * 1536, GH, hout);
    }
}